// round 12
// baseline (speedup 1.0000x reference)
#include <cuda_runtime.h>
#include <math.h>

// Problem constants (fixed by reference: B=32768, D=512)
#define BSZ 32768
#define DSZ 512
#define ROWS_PER_BLOCK 16
#define NBLOCKS (BSZ / ROWS_PER_BLOCK)   // 2048
#define NTHREADS 256
#define F4_PER_ROW (DSZ / 4)             // 128
#define NSTAGES 8                        // 2048 float4 per block / 256 threads

__device__ float g_partials[NBLOCKS];
__device__ int   g_count;   // zero-init; reset to 0 by last block each launch

__device__ __forceinline__ void cp_async16(void* smem_dst, const void* gmem_src) {
    unsigned saddr = (unsigned)__cvta_generic_to_shared(smem_dst);
    asm volatile("cp.async.cg.shared.global [%0], [%1], 16;\n"
                 :: "r"(saddr), "l"(gmem_src));
}
#define CP_COMMIT()  asm volatile("cp.async.commit_group;\n" ::: "memory")
#define CP_WAIT(N)   asm volatile("cp.async.wait_group %0;\n" :: "n"(N) : "memory")

__global__ void __launch_bounds__(NTHREADS)
fused_loss_kernel(const float4* __restrict__ inp,
                  const float4* __restrict__ lab,
                  const float*  __restrict__ ea,
                  const int*    __restrict__ attribute,
                  const float*  __restrict__ attribute_num,
                  float* __restrict__ out) {
    __shared__ float4 sa[NSTAGES][NTHREADS];   // 32 KB: ALL inp stages resident
    __shared__ float  sw[ROWS_PER_BLOCK];
    __shared__ float  sdata[NTHREADS];

    const int tid = threadIdx.x;
    const int row0 = blockIdx.x * ROWS_PER_BLOCK;
    const float4* ga = inp + row0 * F4_PER_ROW + tid;
    const float4* gb = lab + row0 * F4_PER_ROW + tid;

    // ---- inp: issue ALL 8 stages up front (max front-batched depth) ----
#pragma unroll
    for (int k = 0; k < NSTAGES; k++) {
        cp_async16(&sa[k][tid], ga + k * NTHREADS);
        CP_COMMIT();
    }
    // ---- label: register prefetch, distance 3 ----
    float4 b0 = __ldcs(gb + 0 * NTHREADS);
    float4 b1 = __ldcs(gb + 1 * NTHREADS);
    float4 b2 = __ldcs(gb + 2 * NTHREADS);

    // ---- per-row weights for this block's 16 rows (threads 0..15) ----
    if (tid < ROWS_PER_BLOCK) {
        const int b = row0 + tid;
        float s = attribute_num[0] + attribute_num[1] + attribute_num[2]
                + attribute_num[3] + attribute_num[4] + attribute_num[5];
        float attr_w = 0.0f;
#pragma unroll
        for (int j = 0; j < 6; j++) {
            if (attribute[b * 6 + j] == 1) attr_w += s / attribute_num[j];
        }
        float angle_w = 3.0f - cosf(ea[b * 3 + 0])
                             - cosf(ea[b * 3 + 1])
                             - cosf(ea[b * 3 + 2]);
        sw[tid] = angle_w * attr_w;
    }
    __syncthreads();   // publish sw; async pipeline unaffected

    const int wbase = tid >> 7;              // 0 or 1 (128 float4 per row)
    float acc = 0.0f;

    // STAGE(k, waitn): consume inp stage k once <= waitn groups remain pending.
    // LOADB: optional label prefetch roll for stages 0..4 (loads index k+3).
#define STAGE(k, waitn, LOADB)                                         \
    {                                                                  \
        CP_WAIT(waitn);                                                \
        const float4 a = sa[k][tid];                                   \
        const float w = sw[(k) * 2 + wbase];                           \
        const float dx = a.x - b0.x, dy = a.y - b0.y;                  \
        const float dz = a.z - b0.z, dw = a.w - b0.w;                  \
        acc += w * (dx * dx + dy * dy + dz * dz + dw * dw);            \
        LOADB                                                          \
    }
#define ROLLB(nextk) b0 = b1; b1 = b2; b2 = __ldcs(gb + (nextk) * NTHREADS);
#define SHIFTB()     b0 = b1; b1 = b2;
#define NOB()

    STAGE(0, 7, ROLLB(3))
    STAGE(1, 6, ROLLB(4))
    STAGE(2, 5, ROLLB(5))
    STAGE(3, 4, ROLLB(6))
    STAGE(4, 3, ROLLB(7))
    STAGE(5, 2, SHIFTB())
    STAGE(6, 1, SHIFTB())
    STAGE(7, 0, NOB())

#undef STAGE
#undef ROLLB
#undef SHIFTB
#undef NOB

    // ---- block tree-reduce ----
    sdata[tid] = acc;
    __syncthreads();
#pragma unroll
    for (int off = NTHREADS / 2; off >= 32; off >>= 1) {
        if (tid < off) sdata[tid] += sdata[tid + off];
        __syncthreads();
    }
    if (tid < 32) {
        float v = sdata[tid];
#pragma unroll
        for (int off = 16; off > 0; off >>= 1)
            v += __shfl_down_sync(0xFFFFFFFF, v, off);
        if (tid == 0) g_partials[blockIdx.x] = v;
    }

    // ---- last-block-done final reduce (deterministic fixed-order sum) ----
    __shared__ bool is_last;
    if (tid == 0) {
        __threadfence();                          // publish g_partials
        int old = atomicAdd(&g_count, 1);
        is_last = (old == NBLOCKS - 1);
    }
    __syncthreads();
    if (!is_last) return;

    float v = 0.0f;
#pragma unroll
    for (int k = 0; k < NBLOCKS / NTHREADS; k++)  // 8 fixed-order terms
        v += g_partials[tid + k * NTHREADS];
    sdata[tid] = v;
    __syncthreads();
#pragma unroll
    for (int off = NTHREADS / 2; off >= 32; off >>= 1) {
        if (tid < off) sdata[tid] += sdata[tid + off];
        __syncthreads();
    }
    if (tid < 32) {
        float s2 = sdata[tid];
#pragma unroll
        for (int off = 16; off > 0; off >>= 1)
            s2 += __shfl_down_sync(0xFFFFFFFF, s2, off);
        if (tid == 0) {
            out[0] = s2 * (1.0f / (float)(BSZ * DSZ));
            g_count = 0;   // reset so graph replay is deterministic
        }
    }
}

// ---------------------------------------------------------------------------
// kernel_launch — input order: inp, label, ea, attribute, attribute_num,
// batch_size
// ---------------------------------------------------------------------------
extern "C" void kernel_launch(void* const* d_in, const int* in_sizes, int n_in,
                              void* d_out, int out_size) {
    const float* inp  = (const float*)d_in[0];
    const float* lab  = (const float*)d_in[1];
    const float* ea   = (const float*)d_in[2];
    const int*   attr = (const int*)d_in[3];
    const float* anum = (const float*)d_in[4];
    float* out = (float*)d_out;

    fused_loss_kernel<<<NBLOCKS, NTHREADS>>>((const float4*)inp,
                                             (const float4*)lab,
                                             ea, attr, anum, out);
}

// round 15
// speedup vs baseline: 1.1563x; 1.1563x over previous
#include <cuda_runtime.h>
#include <math.h>

// Problem constants (fixed by reference: B=32768, D=512)
#define BSZ 32768
#define DSZ 512
#define ROWS_PER_BLOCK 16
#define NBLOCKS (BSZ / ROWS_PER_BLOCK)   // 2048
#define NTHREADS 256
#define F4_PER_ROW (DSZ / 4)             // 128
#define NSTAGES 8                        // 2048 float4 per block / 256 threads
#define DEPTH 4                          // cp.async rolling pipeline depth (inp)

__device__ float g_partials[NBLOCKS];
__device__ int   g_count;   // zero-init; reset to 0 by last block each launch

__device__ __forceinline__ void cp_async16(void* smem_dst, const void* gmem_src) {
    unsigned saddr = (unsigned)__cvta_generic_to_shared(smem_dst);
    asm volatile("cp.async.cg.shared.global [%0], [%1], 16;\n"
                 :: "r"(saddr), "l"(gmem_src));
}
#define CP_COMMIT()  asm volatile("cp.async.commit_group;\n" ::: "memory")
#define CP_WAIT(N)   asm volatile("cp.async.wait_group %0;\n" :: "n"(N) : "memory")

__global__ void __launch_bounds__(NTHREADS)
fused_loss_kernel(const float4* __restrict__ inp,
                  const float4* __restrict__ lab,
                  const float*  __restrict__ ea,
                  const int*    __restrict__ attribute,
                  const float*  __restrict__ attribute_num,
                  float* __restrict__ out) {
    __shared__ float4 sa[DEPTH][NTHREADS];   // 16 KB (inp rolling pipeline)
    __shared__ float  sw[ROWS_PER_BLOCK];
    __shared__ float  sdata[NTHREADS];

    const int tid = threadIdx.x;
    const int row0 = blockIdx.x * ROWS_PER_BLOCK;
    const float4* ga = inp + row0 * F4_PER_ROW + tid;
    const float4* gb = lab + row0 * F4_PER_ROW + tid;

    // ---- inp: issue first DEPTH pipeline stages ----
#pragma unroll
    for (int k = 0; k < DEPTH; k++) {
        cp_async16(&sa[k][tid], ga + k * NTHREADS);
        CP_COMMIT();
    }
    // ---- label: register prefetch, distance 4 ----
    float4 b0 = __ldcs(gb + 0 * NTHREADS);
    float4 b1 = __ldcs(gb + 1 * NTHREADS);
    float4 b2 = __ldcs(gb + 2 * NTHREADS);
    float4 b3 = __ldcs(gb + 3 * NTHREADS);

    // ---- per-row weights for this block's 16 rows (threads 0..15) ----
    if (tid < ROWS_PER_BLOCK) {
        const int b = row0 + tid;
        float s = attribute_num[0] + attribute_num[1] + attribute_num[2]
                + attribute_num[3] + attribute_num[4] + attribute_num[5];
        float attr_w = 0.0f;
#pragma unroll
        for (int j = 0; j < 6; j++) {
            if (attribute[b * 6 + j] == 1) attr_w += s / attribute_num[j];
        }
        float angle_w = 3.0f - cosf(ea[b * 3 + 0])
                             - cosf(ea[b * 3 + 1])
                             - cosf(ea[b * 3 + 2]);
        sw[tid] = angle_w * attr_w;
    }
    __syncthreads();   // publish sw; async pipelines unaffected

    const int wbase = tid >> 7;              // 0 or 1 (128 float4 per row)
    float acc = 0.0f;

    // ---- steady state: k = 0..3 (consume stage k, refill stage k+DEPTH) ----
#pragma unroll
    for (int k = 0; k < NSTAGES - DEPTH; k++) {
        CP_WAIT(DEPTH - 1);                       // inp stage k landed
        const float4 a = sa[k % DEPTH][tid];
        const float w = sw[k * 2 + wbase];
        const float dx = a.x - b0.x, dy = a.y - b0.y;
        const float dz = a.z - b0.z, dw = a.w - b0.w;
        acc += w * (dx * dx + dy * dy + dz * dz + dw * dw);
        // roll label prefetch (k+4 <= 7, always in range)
        b0 = b1; b1 = b2; b2 = b3;
        b3 = __ldcs(gb + (k + 4) * NTHREADS);
        // refill inp pipeline slot with stage k+DEPTH (<= 7, in range)
        cp_async16(&sa[k % DEPTH][tid], ga + (k + DEPTH) * NTHREADS);
        CP_COMMIT();
    }
    // ---- drain: stages 4..7 with decreasing allowed-outstanding ----
    {
        CP_WAIT(3);
        const float4 a = sa[4 % DEPTH][tid];
        const float w = sw[4 * 2 + wbase];
        const float dx = a.x - b0.x, dy = a.y - b0.y;
        const float dz = a.z - b0.z, dw = a.w - b0.w;
        acc += w * (dx * dx + dy * dy + dz * dz + dw * dw);
        b0 = b1; b1 = b2; b2 = b3;
    }
    {
        CP_WAIT(2);
        const float4 a = sa[5 % DEPTH][tid];
        const float w = sw[5 * 2 + wbase];
        const float dx = a.x - b0.x, dy = a.y - b0.y;
        const float dz = a.z - b0.z, dw = a.w - b0.w;
        acc += w * (dx * dx + dy * dy + dz * dz + dw * dw);
        b0 = b1; b1 = b2;
    }
    {
        CP_WAIT(1);
        const float4 a = sa[6 % DEPTH][tid];
        const float w = sw[6 * 2 + wbase];
        const float dx = a.x - b0.x, dy = a.y - b0.y;
        const float dz = a.z - b0.z, dw = a.w - b0.w;
        acc += w * (dx * dx + dy * dy + dz * dz + dw * dw);
        b0 = b1;
    }
    {
        CP_WAIT(0);
        const float4 a = sa[7 % DEPTH][tid];
        const float w = sw[7 * 2 + wbase];
        const float dx = a.x - b0.x, dy = a.y - b0.y;
        const float dz = a.z - b0.z, dw = a.w - b0.w;
        acc += w * (dx * dx + dy * dy + dz * dz + dw * dw);
    }

    // ---- block tree-reduce ----
    sdata[tid] = acc;
    __syncthreads();
#pragma unroll
    for (int off = NTHREADS / 2; off >= 32; off >>= 1) {
        if (tid < off) sdata[tid] += sdata[tid + off];
        __syncthreads();
    }
    if (tid < 32) {
        float v = sdata[tid];
#pragma unroll
        for (int off = 16; off > 0; off >>= 1)
            v += __shfl_down_sync(0xFFFFFFFF, v, off);
        if (tid == 0) g_partials[blockIdx.x] = v;
    }

    // ---- last-block-done final reduce (deterministic fixed-order sum) ----
    __shared__ bool is_last;
    if (tid == 0) {
        __threadfence();                          // publish g_partials
        int old = atomicAdd(&g_count, 1);
        is_last = (old == NBLOCKS - 1);
    }
    __syncthreads();
    if (!is_last) return;

    float v = 0.0f;
#pragma unroll
    for (int k = 0; k < NBLOCKS / NTHREADS; k++)  // 8 fixed-order terms
        v += g_partials[tid + k * NTHREADS];
    sdata[tid] = v;
    __syncthreads();
#pragma unroll
    for (int off = NTHREADS / 2; off >= 32; off >>= 1) {
        if (tid < off) sdata[tid] += sdata[tid + off];
        __syncthreads();
    }
    if (tid < 32) {
        float s2 = sdata[tid];
#pragma unroll
        for (int off = 16; off > 0; off >>= 1)
            s2 += __shfl_down_sync(0xFFFFFFFF, s2, off);
        if (tid == 0) {
            out[0] = s2 * (1.0f / (float)(BSZ * DSZ));
            g_count = 0;   // reset so graph replay is deterministic
        }
    }
}

// ---------------------------------------------------------------------------
// kernel_launch — input order: inp, label, ea, attribute, attribute_num,
// batch_size
// ---------------------------------------------------------------------------
extern "C" void kernel_launch(void* const* d_in, const int* in_sizes, int n_in,
                              void* d_out, int out_size) {
    const float* inp  = (const float*)d_in[0];
    const float* lab  = (const float*)d_in[1];
    const float* ea   = (const float*)d_in[2];
    const int*   attr = (const int*)d_in[3];
    const float* anum = (const float*)d_in[4];
    float* out = (float*)d_out;

    fused_loss_kernel<<<NBLOCKS, NTHREADS>>>((const float4*)inp,
                                             (const float4*)lab,
                                             ea, attr, anum, out);
}

// round 17
// speedup vs baseline: 1.1616x; 1.0046x over previous
#include <cuda_runtime.h>
#include <math.h>

// Problem constants (fixed by reference: B=32768, D=512)
#define BSZ 32768
#define DSZ 512
#define ROWS_PER_BLOCK 16
#define NBLOCKS (BSZ / ROWS_PER_BLOCK)   // 2048
#define NTHREADS 256
#define F4_PER_ROW (DSZ / 4)             // 128
#define NSTAGES 8                        // 2048 float4 per block / 256 threads
#define DEPTH 5                          // cp.async rolling pipeline depth (inp)

__device__ float g_partials[NBLOCKS];
__device__ int   g_count;   // zero-init; reset to 0 by last block each launch

__device__ __forceinline__ void cp_async16(void* smem_dst, const void* gmem_src) {
    unsigned saddr = (unsigned)__cvta_generic_to_shared(smem_dst);
    asm volatile("cp.async.cg.shared.global [%0], [%1], 16;\n"
                 :: "r"(saddr), "l"(gmem_src));
}
#define CP_COMMIT()  asm volatile("cp.async.commit_group;\n" ::: "memory")
#define CP_WAIT(N)   asm volatile("cp.async.wait_group %0;\n" :: "n"(N) : "memory")

__global__ void __launch_bounds__(NTHREADS)
fused_loss_kernel(const float4* __restrict__ inp,
                  const float4* __restrict__ lab,
                  const float*  __restrict__ ea,
                  const int*    __restrict__ attribute,
                  const float*  __restrict__ attribute_num,
                  float* __restrict__ out) {
    __shared__ float4 sa[DEPTH][NTHREADS];   // 20 KB (inp rolling pipeline)
    __shared__ float  sw[ROWS_PER_BLOCK];
    __shared__ float  sdata[NTHREADS];

    const int tid = threadIdx.x;
    const int row0 = blockIdx.x * ROWS_PER_BLOCK;
    const float4* ga = inp + row0 * F4_PER_ROW + tid;
    const float4* gb = lab + row0 * F4_PER_ROW + tid;

    // ---- prologue: interleave inp cp.async stages with label LDG prefetch
    //      (staggers the initial request burst at the L1tex queue) ----
    cp_async16(&sa[0][tid], ga + 0 * NTHREADS);  CP_COMMIT();
    float4 b0 = __ldcs(gb + 0 * NTHREADS);
    cp_async16(&sa[1][tid], ga + 1 * NTHREADS);  CP_COMMIT();
    float4 b1 = __ldcs(gb + 1 * NTHREADS);
    cp_async16(&sa[2][tid], ga + 2 * NTHREADS);  CP_COMMIT();
    float4 b2 = __ldcs(gb + 2 * NTHREADS);
    cp_async16(&sa[3][tid], ga + 3 * NTHREADS);  CP_COMMIT();
    cp_async16(&sa[4][tid], ga + 4 * NTHREADS);  CP_COMMIT();

    // ---- per-row weights for this block's 16 rows (threads 0..15) ----
    if (tid < ROWS_PER_BLOCK) {
        const int b = row0 + tid;
        float s = attribute_num[0] + attribute_num[1] + attribute_num[2]
                + attribute_num[3] + attribute_num[4] + attribute_num[5];
        float attr_w = 0.0f;
#pragma unroll
        for (int j = 0; j < 6; j++) {
            if (attribute[b * 6 + j] == 1) attr_w += s / attribute_num[j];
        }
        float angle_w = 3.0f - cosf(ea[b * 3 + 0])
                             - cosf(ea[b * 3 + 1])
                             - cosf(ea[b * 3 + 2]);
        sw[tid] = angle_w * attr_w;
    }
    __syncthreads();   // publish sw; async pipelines unaffected

    const int wbase = tid >> 7;              // 0 or 1 (128 float4 per row)
    float acc = 0.0f;

    // ---- steady state: k = 0..2 (consume stage k, refill stage k+DEPTH) ----
#pragma unroll
    for (int k = 0; k < NSTAGES - DEPTH; k++) {
        CP_WAIT(DEPTH - 1);                       // inp stage k landed
        const float4 a = sa[k % DEPTH][tid];
        const float w = sw[k * 2 + wbase];
        const float dx = a.x - b0.x, dy = a.y - b0.y;
        const float dz = a.z - b0.z, dw = a.w - b0.w;
        acc += w * (dx * dx + dy * dy + dz * dz + dw * dw);
        b0 = b1; b1 = b2;
        b2 = __ldcs(gb + (k + 3) * NTHREADS);     // k+3 <= 5, in range
        cp_async16(&sa[k % DEPTH][tid], ga + (k + DEPTH) * NTHREADS);  // 5..7
        CP_COMMIT();
    }
    // ---- drain: stages 3..7, allowed-outstanding counts down 4..0 ----
#pragma unroll
    for (int k = NSTAGES - DEPTH; k < NSTAGES; k++) {
        switch (NSTAGES - 1 - k) {                // compile-time per unrolled k
            case 4: CP_WAIT(4); break;
            case 3: CP_WAIT(3); break;
            case 2: CP_WAIT(2); break;
            case 1: CP_WAIT(1); break;
            default: CP_WAIT(0); break;
        }
        const float4 a = sa[k % DEPTH][tid];
        const float w = sw[k * 2 + wbase];
        const float dx = a.x - b0.x, dy = a.y - b0.y;
        const float dz = a.z - b0.z, dw = a.w - b0.w;
        acc += w * (dx * dx + dy * dy + dz * dz + dw * dw);
        b0 = b1; b1 = b2;
        if (k + 3 < NSTAGES)                      // compile-time predicate
            b2 = __ldcs(gb + (k + 3) * NTHREADS);
    }

    // ---- block tree-reduce ----
    sdata[tid] = acc;
    __syncthreads();
#pragma unroll
    for (int off = NTHREADS / 2; off >= 32; off >>= 1) {
        if (tid < off) sdata[tid] += sdata[tid + off];
        __syncthreads();
    }
    if (tid < 32) {
        float v = sdata[tid];
#pragma unroll
        for (int off = 16; off > 0; off >>= 1)
            v += __shfl_down_sync(0xFFFFFFFF, v, off);
        if (tid == 0) g_partials[blockIdx.x] = v;
    }

    // ---- last-block-done final reduce (deterministic fixed-order sum) ----
    __shared__ bool is_last;
    if (tid == 0) {
        __threadfence();                          // publish g_partials
        int old = atomicAdd(&g_count, 1);
        is_last = (old == NBLOCKS - 1);
    }
    __syncthreads();
    if (!is_last) return;

    float v = 0.0f;
#pragma unroll
    for (int k = 0; k < NBLOCKS / NTHREADS; k++)  // 8 fixed-order terms
        v += g_partials[tid + k * NTHREADS];
    sdata[tid] = v;
    __syncthreads();
#pragma unroll
    for (int off = NTHREADS / 2; off >= 32; off >>= 1) {
        if (tid < off) sdata[tid] += sdata[tid + off];
        __syncthreads();
    }
    if (tid < 32) {
        float s2 = sdata[tid];
#pragma unroll
        for (int off = 16; off > 0; off >>= 1)
            s2 += __shfl_down_sync(0xFFFFFFFF, s2, off);
        if (tid == 0) {
            out[0] = s2 * (1.0f / (float)(BSZ * DSZ));
            g_count = 0;   // reset so graph replay is deterministic
        }
    }
}

// ---------------------------------------------------------------------------
// kernel_launch — input order: inp, label, ea, attribute, attribute_num,
// batch_size
// ---------------------------------------------------------------------------
extern "C" void kernel_launch(void* const* d_in, const int* in_sizes, int n_in,
                              void* d_out, int out_size) {
    const float* inp  = (const float*)d_in[0];
    const float* lab  = (const float*)d_in[1];
    const float* ea   = (const float*)d_in[2];
    const int*   attr = (const int*)d_in[3];
    const float* anum = (const float*)d_in[4];
    float* out = (float*)d_out;

    fused_loss_kernel<<<NBLOCKS, NTHREADS>>>((const float4*)inp,
                                             (const float4*)lab,
                                             ea, attr, anum, out);
}